// round 2
// baseline (speedup 1.0000x reference)
#include <cuda_runtime.h>
#include <cuda_bf16.h>
#include <cstdint>

#define DI __device__ __forceinline__

static constexpr int B_ROWS = 8192;
static constexpr int DIM    = 1024;
static constexpr int NCOLS  = 16384;   // 2*B

// GEMM tiling
static constexpr int MT = 128;
static constexpr int NT = 128;
static constexpr int KC = 64;                  // bf16 elems per K chunk (128 B rows)
static constexpr int NCHUNK = DIM / KC;        // 16

// stage: A_hi, A_lo, B_hi, B_lo each 128 rows x 128 bytes = 16 KB
static constexpr int TILE_BYTES  = 128 * 128;          // 16384
static constexpr int STAGE_BYTES = 4 * TILE_BYTES;     // 64 KB
static constexpr int SMEM_BYTES  = 2 * STAGE_BYTES;    // 128 KB

// -------- scratch (static device arrays; no allocation) --------
__device__ __nv_bfloat16 g_a_hi[B_ROWS * DIM];
__device__ __nv_bfloat16 g_a_lo[B_ROWS * DIM];
__device__ __nv_bfloat16 g_e_hi[B_ROWS * DIM];
__device__ __nv_bfloat16 g_e_lo[B_ROWS * DIM];
__device__ __nv_bfloat16 g_c_hi[B_ROWS * DIM];
__device__ __nv_bfloat16 g_c_lo[B_ROWS * DIM];
__device__ float g_rowloss[B_ROWS];

// -------- helpers --------
DI uint32_t smem_u32(const void* p) {
    uint32_t a;
    asm("{ .reg .u64 t; cvta.to.shared.u64 t, %1; cvt.u32.u64 %0, t; }" : "=r"(a) : "l"(p));
    return a;
}
DI uint32_t swz(uint32_t off) { return off ^ ((off >> 3) & 0x70); }

DI void cp_async16(uint32_t dst, const void* src) {
    asm volatile("cp.async.cg.shared.global [%0], [%1], 16;" :: "r"(dst), "l"(src) : "memory");
}
#define CP_COMMIT() asm volatile("cp.async.commit_group;" ::: "memory")
#define CP_WAIT(n)  asm volatile("cp.async.wait_group %0;" :: "n"(n) : "memory")

DI void ldsm4(uint32_t* r, uint32_t addr) {
    asm volatile("ldmatrix.sync.aligned.m8n8.x4.shared.b16 {%0,%1,%2,%3}, [%4];"
                 : "=r"(r[0]), "=r"(r[1]), "=r"(r[2]), "=r"(r[3]) : "r"(addr));
}

DI void mma_bf16(float* c, const uint32_t* a, const uint32_t* b) {
    asm volatile(
        "mma.sync.aligned.m16n8k16.row.col.f32.bf16.bf16.f32 "
        "{%0,%1,%2,%3}, {%4,%5,%6,%7}, {%8,%9}, {%0,%1,%2,%3};"
        : "+f"(c[0]), "+f"(c[1]), "+f"(c[2]), "+f"(c[3])
        : "r"(a[0]), "r"(a[1]), "r"(a[2]), "r"(a[3]), "r"(b[0]), "r"(b[1]));
}

// -------- block reduce (sum) for 256-thread blocks --------
DI float block_sum256(float v) {
    __shared__ float red[8];
    #pragma unroll
    for (int o = 16; o; o >>= 1) v += __shfl_xor_sync(0xFFFFFFFFu, v, o);
    if ((threadIdx.x & 31) == 0) red[threadIdx.x >> 5] = v;
    __syncthreads();
    if (threadIdx.x < 8) {
        v = red[threadIdx.x];
        #pragma unroll
        for (int o = 4; o; o >>= 1) v += __shfl_xor_sync(0xFFu, v, o);
        if (threadIdx.x == 0) red[0] = v;
    }
    __syncthreads();
    return red[0];
}

// ============ Kernel 1: L2-normalize rows, split to bf16 hi/lo ============
// premise rows additionally scaled by 1/TEMP = 20 so the GEMM emits sims directly.
__global__ void __launch_bounds__(256) norm_split_kernel(
    const float* __restrict__ p, const float* __restrict__ e, const float* __restrict__ c)
{
    int row = blockIdx.x;
    const float* src;
    __nv_bfloat16 *hi, *lo;
    float extra = 1.0f;
    if (row < B_ROWS) {
        src = p + (size_t)row * DIM; hi = g_a_hi + (size_t)row * DIM; lo = g_a_lo + (size_t)row * DIM;
        extra = 20.0f;
    } else if (row < 2 * B_ROWS) {
        int r = row - B_ROWS;
        src = e + (size_t)r * DIM; hi = g_e_hi + (size_t)r * DIM; lo = g_e_lo + (size_t)r * DIM;
    } else {
        int r = row - 2 * B_ROWS;
        src = c + (size_t)r * DIM; hi = g_c_hi + (size_t)r * DIM; lo = g_c_lo + (size_t)r * DIM;
    }
    float4 x = reinterpret_cast<const float4*>(src)[threadIdx.x];
    float ss = x.x * x.x + x.y * x.y + x.z * x.z + x.w * x.w;
    float tot = block_sum256(ss);
    float scale = extra / fmaxf(sqrtf(tot), 1e-8f);

    float v[4] = {x.x * scale, x.y * scale, x.z * scale, x.w * scale};
    #pragma unroll
    for (int j = 0; j < 4; j++) {
        __nv_bfloat16 h = __float2bfloat16(v[j]);
        __nv_bfloat16 l = __float2bfloat16(v[j] - __bfloat162float(h));
        hi[threadIdx.x * 4 + j] = h;
        lo[threadIdx.x * 4 + j] = l;
    }
}

// ============ Kernel 2: HMMA GEMM, 3-term bf16 split -> sims ============
// 256 threads, CTA tile 128x128, warp tile 64(M)x32(N), warps 2(M)x4(N).
__global__ void __launch_bounds__(256, 1) gemm_kernel(float* __restrict__ out) {
    extern __shared__ char smem[];
    uint32_t sb = smem_u32(smem);
    int tid = threadIdx.x, w = tid >> 5, lane = tid & 31;

    // supertile swizzle: groups of 8 M-tiles, sweep N within a group
    int sid = blockIdx.x;
    int group  = sid >> 10;        // / (8*128)
    int within = sid & 1023;
    int mt = (group << 3) + (within & 7);
    int nt = within >> 3;
    int m0 = mt * MT, n0 = nt * NT;

    int wm = w & 1, wn = w >> 1;
    int warp_m = wm * 64, warp_n = wn * 32;

    float acc[4][4][4];
    #pragma unroll
    for (int a = 0; a < 4; a++)
        #pragma unroll
        for (int b = 0; b < 4; b++)
            #pragma unroll
            for (int k = 0; k < 4; k++) acc[a][b][k] = 0.0f;

    // ---- stage loader (16 cp.async of 16B per thread) ----
    #define LOAD_STAGE(chunk_) do {                                              \
        int s_ = (chunk_) & 1;                                                   \
        uint32_t stage_ = sb + s_ * STAGE_BYTES;                                 \
        int k0_ = (chunk_) * KC;                                                 \
        _Pragma("unroll")                                                        \
        for (int i_ = 0; i_ < 16; i_++) {                                        \
            int q_ = tid + i_ * 256;                                             \
            int quad_ = q_ >> 10; int idx_ = q_ & 1023;                          \
            int r_ = idx_ >> 3, kc_ = idx_ & 7;                                  \
            const __nv_bfloat16* src_;                                           \
            if (quad_ == 0)      src_ = g_a_hi + (size_t)(m0 + r_) * DIM + k0_ + kc_ * 8; \
            else if (quad_ == 1) src_ = g_a_lo + (size_t)(m0 + r_) * DIM + k0_ + kc_ * 8; \
            else {                                                               \
                int col_ = n0 + r_;                                              \
                const __nv_bfloat16* base_ = (col_ < B_ROWS)                     \
                    ? (quad_ == 2 ? g_e_hi : g_e_lo)                             \
                    : (quad_ == 2 ? g_c_hi : g_c_lo);                            \
                src_ = base_ + (size_t)(col_ & (B_ROWS - 1)) * DIM + k0_ + kc_ * 8; \
            }                                                                    \
            uint32_t dst_ = stage_ + quad_ * TILE_BYTES + swz(r_ * 128 + kc_ * 16); \
            cp_async16(dst_, src_);                                              \
        }                                                                        \
        CP_COMMIT();                                                             \
    } while (0)

    LOAD_STAGE(0);

    for (int chunk = 0; chunk < NCHUNK; ++chunk) {
        if (chunk + 1 < NCHUNK) { LOAD_STAGE(chunk + 1); CP_WAIT(1); }
        else                    { CP_WAIT(0); }
        __syncthreads();

        uint32_t stage = sb + (chunk & 1) * STAGE_BYTES;
        uint32_t Ahi = stage, Alo = stage + TILE_BYTES;
        uint32_t Bhi = stage + 2 * TILE_BYTES, Blo = stage + 3 * TILE_BYTES;

        int arow = warp_m + (lane & 15);
        int acol = (lane >> 4);                       // 0/1 -> k half
        int brow = (lane & 7) + ((lane >> 4) << 3);   // n within 16
        int bkh  = (lane >> 3) & 1;                   // k half

        #pragma unroll
        for (int kk = 0; kk < 4; kk++) {
            uint32_t a_hi[4][4], a_lo[4][4];
            #pragma unroll
            for (int mb = 0; mb < 4; mb++) {
                uint32_t off = swz((uint32_t)(arow + mb * 16) * 128 + kk * 32 + acol * 16);
                ldsm4(a_hi[mb], Ahi + off);
                ldsm4(a_lo[mb], Alo + off);
            }
            uint32_t b_hi[2][4], b_lo[2][4];
            #pragma unroll
            for (int p = 0; p < 2; p++) {
                uint32_t off = swz((uint32_t)(warp_n + p * 16 + brow) * 128 + kk * 32 + bkh * 16);
                ldsm4(b_hi[p], Bhi + off);
                ldsm4(b_lo[p], Blo + off);
            }
            #pragma unroll
            for (int mb = 0; mb < 4; mb++)
                #pragma unroll
                for (int p = 0; p < 2; p++)
                    #pragma unroll
                    for (int sub = 0; sub < 2; sub++) {
                        float* c = acc[mb][p * 2 + sub];
                        mma_bf16(c, a_hi[mb], &b_hi[p][sub * 2]);
                        mma_bf16(c, a_hi[mb], &b_lo[p][sub * 2]);
                        mma_bf16(c, a_lo[mb], &b_hi[p][sub * 2]);
                    }
        }
        __syncthreads();
    }

    // ---- epilogue: direct stores (32B-sector coalesced) ----
    float* o = out + 1;
    #pragma unroll
    for (int mb = 0; mb < 4; mb++) {
        int row = m0 + warp_m + mb * 16 + (lane >> 2);
        #pragma unroll
        for (int nb = 0; nb < 4; nb++) {
            int col = n0 + warp_n + nb * 8 + (lane & 3) * 2;
            float* p0 = o + (size_t)row * NCOLS + col;
            p0[0] = acc[mb][nb][0];
            p0[1] = acc[mb][nb][1];
            float* p1 = p0 + (size_t)8 * NCOLS;
            p1[0] = acc[mb][nb][2];
            p1[1] = acc[mb][nb][3];
        }
    }
    #undef LOAD_STAGE
}

// ============ Kernel 3: row logsumexp (single pass; sims <= 20 analytically) ============
DI float exp_poly(float v) {                 // e^v for v in [-40, ~1e-3]
    float t = v * 1.4426950408889634f;
    float fi = floorf(t);
    float f = t - fi;
    float p = 1.5403530393283441e-4f;        // 2^f, degree-6 Taylor
    p = p * f + 1.3333558146428443e-3f;
    p = p * f + 9.6181291076284771e-3f;
    p = p * f + 5.5504108664821580e-2f;
    p = p * f + 2.4022650695910071e-1f;
    p = p * f + 6.9314718055994531e-1f;
    p = p * f + 1.0f;
    return __int_as_float(((int)fi + 127) << 23) * p;
}

__global__ void __launch_bounds__(256) lse_kernel(const float* __restrict__ sims) {
    int row = blockIdx.x;
    const float* x = sims + (size_t)row * NCOLS;
    float s = 0.0f;
    #pragma unroll 8
    for (int j = threadIdx.x; j < NCOLS; j += 256)
        s += exp_poly(x[j] - 20.0f);
    float tot = block_sum256(s);
    if (threadIdx.x == 0)
        g_rowloss[row] = 20.0f + logf(tot) - x[row];   // logz - tgt (diag of first half)
}

// ============ Kernel 4: deterministic mean ============
__global__ void __launch_bounds__(256) loss_kernel(float* __restrict__ out) {
    float s = 0.0f;
    for (int i = threadIdx.x; i < B_ROWS; i += 256) s += g_rowloss[i];
    float tot = block_sum256(s);
    if (threadIdx.x == 0) out[0] = tot * (1.0f / (float)B_ROWS);
}

// ============ launch ============
extern "C" void kernel_launch(void* const* d_in, const int* in_sizes, int n_in,
                              void* d_out, int out_size) {
    (void)in_sizes; (void)n_in; (void)out_size;
    const float* p = (const float*)d_in[0];
    const float* e = (const float*)d_in[1];
    const float* c = (const float*)d_in[2];
    float* out = (float*)d_out;

    norm_split_kernel<<<3 * B_ROWS, 256>>>(p, e, c);

    cudaFuncSetAttribute(gemm_kernel, cudaFuncAttributeMaxDynamicSharedMemorySize, SMEM_BYTES);
    gemm_kernel<<<(B_ROWS / MT) * (NCOLS / NT), 256, SMEM_BYTES>>>(out);

    lse_kernel<<<B_ROWS, 256>>>(out + 1);
    loss_kernel<<<1, 256>>>(out);
}

// round 3
// speedup vs baseline: 1.3523x; 1.3523x over previous
#include <cuda_runtime.h>
#include <cuda_fp16.h>
#include <cstdint>

#define DI __device__ __forceinline__

static constexpr int B_ROWS = 8192;
static constexpr int DIM    = 1024;
static constexpr int NCOLS  = 16384;   // 2*B
static constexpr int NTILE  = 128;     // NCOLS / NT

// GEMM tiling
static constexpr int MT = 128;
static constexpr int NT = 128;
static constexpr int KC = 64;                  // fp16 elems per K chunk (128 B rows)
static constexpr int NCHUNK = DIM / KC;        // 16

// stage: A_hi, A_lo, B each 128 rows x 128 bytes = 16 KB
static constexpr int TILE_BYTES  = 128 * 128;          // 16384
static constexpr int STAGE_BYTES = 3 * TILE_BYTES;     // 48 KB
static constexpr int SMEM_BYTES  = 2 * STAGE_BYTES;    // 96 KB

// -------- scratch (static device arrays; no allocation) --------
__device__ __half g_a_hi[B_ROWS * DIM];
__device__ __half g_a_lo[B_ROWS * DIM];
__device__ __half g_b_hi[(size_t)NCOLS * DIM];    // entail rows then contra rows
__device__ float  g_part[(size_t)B_ROWS * NTILE]; // per (row, n-tile) sum of exp(sim-20)
__device__ float  g_rowloss[B_ROWS];

// -------- helpers --------
DI uint32_t smem_u32(const void* p) {
    uint32_t a;
    asm("{ .reg .u64 t; cvta.to.shared.u64 t, %1; cvt.u32.u64 %0, t; }" : "=r"(a) : "l"(p));
    return a;
}
DI uint32_t swz(uint32_t off) { return off ^ ((off >> 3) & 0x70); }

DI void cp_async16(uint32_t dst, const void* src) {
    asm volatile("cp.async.cg.shared.global [%0], [%1], 16;" :: "r"(dst), "l"(src) : "memory");
}
#define CP_COMMIT() asm volatile("cp.async.commit_group;" ::: "memory")
#define CP_WAIT(n)  asm volatile("cp.async.wait_group %0;" :: "n"(n) : "memory")

DI void ldsm4(uint32_t* r, uint32_t addr) {
    asm volatile("ldmatrix.sync.aligned.m8n8.x4.shared.b16 {%0,%1,%2,%3}, [%4];"
                 : "=r"(r[0]), "=r"(r[1]), "=r"(r[2]), "=r"(r[3]) : "r"(addr));
}

DI void mma_f16(float* c, const uint32_t* a, const uint32_t* b) {
    asm volatile(
        "mma.sync.aligned.m16n8k16.row.col.f32.f16.f16.f32 "
        "{%0,%1,%2,%3}, {%4,%5,%6,%7}, {%8,%9}, {%0,%1,%2,%3};"
        : "+f"(c[0]), "+f"(c[1]), "+f"(c[2]), "+f"(c[3])
        : "r"(a[0]), "r"(a[1]), "r"(a[2]), "r"(a[3]), "r"(b[0]), "r"(b[1]));
}

// -------- block reduce (sum) for 256-thread blocks --------
DI float block_sum256(float v) {
    __shared__ float red[8];
    #pragma unroll
    for (int o = 16; o; o >>= 1) v += __shfl_xor_sync(0xFFFFFFFFu, v, o);
    if ((threadIdx.x & 31) == 0) red[threadIdx.x >> 5] = v;
    __syncthreads();
    if (threadIdx.x < 8) {
        v = red[threadIdx.x];
        #pragma unroll
        for (int o = 4; o; o >>= 1) v += __shfl_xor_sync(0xFFu, v, o);
        if (threadIdx.x == 0) red[0] = v;
    }
    __syncthreads();
    return red[0];
}

// ============ Kernel 1: L2-normalize rows -> fp16 ============
// premise: scaled by 1/TEMP=20, exact 2-term fp16 split (hi+lo).
// entail/contra: single fp16 rounding into contiguous g_b_hi.
__global__ void __launch_bounds__(256) norm_split_kernel(
    const float* __restrict__ p, const float* __restrict__ e, const float* __restrict__ c)
{
    int row = blockIdx.x;
    const float* src;
    if (row < B_ROWS)              src = p + (size_t)row * DIM;
    else if (row < 2 * B_ROWS)     src = e + (size_t)(row - B_ROWS) * DIM;
    else                           src = c + (size_t)(row - 2 * B_ROWS) * DIM;

    float4 x = reinterpret_cast<const float4*>(src)[threadIdx.x];
    float ss = x.x * x.x + x.y * x.y + x.z * x.z + x.w * x.w;
    float tot = block_sum256(ss);
    bool is_a = (row < B_ROWS);
    float scale = (is_a ? 20.0f : 1.0f) / fmaxf(sqrtf(tot), 1e-8f);

    float v[4] = {x.x * scale, x.y * scale, x.z * scale, x.w * scale};
    if (is_a) {
        __half *hi = g_a_hi + (size_t)row * DIM, *lo = g_a_lo + (size_t)row * DIM;
        #pragma unroll
        for (int j = 0; j < 4; j++) {
            __half h = __float2half_rn(v[j]);
            __half l = __float2half_rn(v[j] - __half2float(h));
            hi[threadIdx.x * 4 + j] = h;
            lo[threadIdx.x * 4 + j] = l;
        }
    } else {
        __half* dst = g_b_hi + (size_t)(row - B_ROWS) * DIM;
        #pragma unroll
        for (int j = 0; j < 4; j++) dst[threadIdx.x * 4 + j] = __float2half_rn(v[j]);
    }
}

// ============ Kernel 2: fp16 HMMA GEMM (2 terms) + fused partial LSE ============
// 256 threads, CTA tile 128x128, warp tile 64(M)x32(N), warps 2(M)x4(N).
__global__ void __launch_bounds__(256, 1) gemm_kernel(float* __restrict__ out) {
    extern __shared__ char smem[];
    uint32_t sb = smem_u32(smem);
    int tid = threadIdx.x, w = tid >> 5, lane = tid & 31;

    // supertile swizzle: groups of 8 M-tiles, sweep N within a group
    int sid = blockIdx.x;
    int group  = sid >> 10;        // / (8*128)
    int within = sid & 1023;
    int mt = (group << 3) + (within & 7);
    int nt = within >> 3;
    int m0 = mt * MT, n0 = nt * NT;

    int wm = w & 1, wn = w >> 1;
    int warp_m = wm * 64, warp_n = wn * 32;

    float acc[4][4][4];
    #pragma unroll
    for (int a = 0; a < 4; a++)
        #pragma unroll
        for (int b = 0; b < 4; b++)
            #pragma unroll
            for (int k = 0; k < 4; k++) acc[a][b][k] = 0.0f;

    // ---- stage loader (12 cp.async of 16B per thread) ----
    #define LOAD_STAGE(chunk_) do {                                              \
        int s_ = (chunk_) & 1;                                                   \
        uint32_t stage_ = sb + s_ * STAGE_BYTES;                                 \
        int k0_ = (chunk_) * KC;                                                 \
        _Pragma("unroll")                                                        \
        for (int i_ = 0; i_ < 12; i_++) {                                        \
            int q_ = tid + i_ * 256;                                             \
            int quad_ = q_ >> 10; int idx_ = q_ & 1023;                          \
            int r_ = idx_ >> 3, kc_ = idx_ & 7;                                  \
            const __half* src_;                                                  \
            if (quad_ == 0)      src_ = g_a_hi + (size_t)(m0 + r_) * DIM + k0_ + kc_ * 8; \
            else if (quad_ == 1) src_ = g_a_lo + (size_t)(m0 + r_) * DIM + k0_ + kc_ * 8; \
            else                 src_ = g_b_hi + (size_t)(n0 + r_) * DIM + k0_ + kc_ * 8; \
            uint32_t dst_ = stage_ + quad_ * TILE_BYTES + swz(r_ * 128 + kc_ * 16); \
            cp_async16(dst_, src_);                                              \
        }                                                                        \
        CP_COMMIT();                                                             \
    } while (0)

    LOAD_STAGE(0);

    for (int chunk = 0; chunk < NCHUNK; ++chunk) {
        if (chunk + 1 < NCHUNK) { LOAD_STAGE(chunk + 1); CP_WAIT(1); }
        else                    { CP_WAIT(0); }
        __syncthreads();

        uint32_t stage = sb + (chunk & 1) * STAGE_BYTES;
        uint32_t Ahi = stage, Alo = stage + TILE_BYTES, Bhi = stage + 2 * TILE_BYTES;

        int arow = warp_m + (lane & 15);
        int acol = (lane >> 4);                       // 0/1 -> k half
        int brow = (lane & 7) + ((lane >> 4) << 3);   // n within 16
        int bkh  = (lane >> 3) & 1;                   // k half

        #pragma unroll
        for (int kk = 0; kk < 4; kk++) {
            uint32_t a_hi[4][4], a_lo[4][4];
            #pragma unroll
            for (int mb = 0; mb < 4; mb++) {
                uint32_t off = swz((uint32_t)(arow + mb * 16) * 128 + kk * 32 + acol * 16);
                ldsm4(a_hi[mb], Ahi + off);
                ldsm4(a_lo[mb], Alo + off);
            }
            uint32_t b_hi[2][4];
            #pragma unroll
            for (int p = 0; p < 2; p++) {
                uint32_t off = swz((uint32_t)(warp_n + p * 16 + brow) * 128 + kk * 32 + bkh * 16);
                ldsm4(b_hi[p], Bhi + off);
            }
            #pragma unroll
            for (int mb = 0; mb < 4; mb++)
                #pragma unroll
                for (int p = 0; p < 2; p++)
                    #pragma unroll
                    for (int sub = 0; sub < 2; sub++) {
                        float* c = acc[mb][p * 2 + sub];
                        mma_f16(c, a_hi[mb], &b_hi[p][sub * 2]);
                        mma_f16(c, a_lo[mb], &b_hi[p][sub * 2]);
                    }
        }
        __syncthreads();
    }

    // ---- epilogue 1: store sims ----
    float* o = out + 1;
    #pragma unroll
    for (int mb = 0; mb < 4; mb++) {
        int row = m0 + warp_m + mb * 16 + (lane >> 2);
        #pragma unroll
        for (int nb = 0; nb < 4; nb++) {
            int col = n0 + warp_n + nb * 8 + (lane & 3) * 2;
            float* p0 = o + (size_t)row * NCOLS + col;
            p0[0] = acc[mb][nb][0];
            p0[1] = acc[mb][nb][1];
            float* p1 = p0 + (size_t)8 * NCOLS;
            p1[0] = acc[mb][nb][2];
            p1[1] = acc[mb][nb][3];
        }
    }

    // ---- epilogue 2: fused partial logsumexp (sum of exp(sim - 20)) ----
    // exp_poly: e^v for v in [-45, ~1e-2]
    auto exp_poly = [](float v) -> float {
        float t = v * 1.4426950408889634f;
        float fi = floorf(t);
        float f = t - fi;
        float p = 1.5403530393283441e-4f;
        p = p * f + 1.3333558146428443e-3f;
        p = p * f + 9.6181291076284771e-3f;
        p = p * f + 5.5504108664821580e-2f;
        p = p * f + 2.4022650695910071e-1f;
        p = p * f + 6.9314718055994531e-1f;
        p = p * f + 1.0f;
        return __int_as_float(((int)fi + 127) << 23) * p;
    };

    float s[8];
    #pragma unroll
    for (int i = 0; i < 8; i++) s[i] = 0.0f;
    #pragma unroll
    for (int mb = 0; mb < 4; mb++)
        #pragma unroll
        for (int nb = 0; nb < 4; nb++) {
            s[mb * 2 + 0] += exp_poly(acc[mb][nb][0] - 20.0f) + exp_poly(acc[mb][nb][1] - 20.0f);
            s[mb * 2 + 1] += exp_poly(acc[mb][nb][2] - 20.0f) + exp_poly(acc[mb][nb][3] - 20.0f);
        }
    // reduce across the 4 lanes of each quad (they share the same rows)
    #pragma unroll
    for (int i = 0; i < 8; i++) {
        s[i] += __shfl_xor_sync(0xFFFFFFFFu, s[i], 1);
        s[i] += __shfl_xor_sync(0xFFFFFFFFu, s[i], 2);
    }
    // cross-warp reduce via smem (fixed order -> deterministic)
    float* sred = reinterpret_cast<float*>(smem);   // [4 wn][128 rows]
    if ((lane & 3) == 0) {
        #pragma unroll
        for (int mb = 0; mb < 4; mb++) {
            int rl = warp_m + mb * 16 + (lane >> 2);
            sred[wn * 128 + rl]     = s[mb * 2 + 0];
            sred[wn * 128 + rl + 8] = s[mb * 2 + 1];
        }
    }
    __syncthreads();
    if (tid < 128) {
        float t = (sred[tid] + sred[128 + tid]) + (sred[256 + tid] + sred[384 + tid]);
        g_part[(size_t)(m0 + tid) * NTILE + nt] = t;
    }
    #undef LOAD_STAGE
}

// ============ Kernel 3: row loss from partials ============
__global__ void __launch_bounds__(256) lse_kernel(const float* __restrict__ sims) {
    int w = threadIdx.x >> 5, lane = threadIdx.x & 31;
    int row = blockIdx.x * 8 + w;
    const float* pr = g_part + (size_t)row * NTILE;
    float s = (pr[lane] + pr[lane + 32]) + (pr[lane + 64] + pr[lane + 96]);
    #pragma unroll
    for (int o = 16; o; o >>= 1) s += __shfl_xor_sync(0xFFFFFFFFu, s, o);
    if (lane == 0) {
        float diag = sims[(size_t)row * NCOLS + row];
        g_rowloss[row] = 20.0f + logf(s) - diag;
    }
}

// ============ Kernel 4: deterministic mean ============
__global__ void __launch_bounds__(256) loss_kernel(float* __restrict__ out) {
    float s = 0.0f;
    for (int i = threadIdx.x; i < B_ROWS; i += 256) s += g_rowloss[i];
    float tot = block_sum256(s);
    if (threadIdx.x == 0) out[0] = tot * (1.0f / (float)B_ROWS);
}

// ============ launch ============
extern "C" void kernel_launch(void* const* d_in, const int* in_sizes, int n_in,
                              void* d_out, int out_size) {
    (void)in_sizes; (void)n_in; (void)out_size;
    const float* p = (const float*)d_in[0];
    const float* e = (const float*)d_in[1];
    const float* c = (const float*)d_in[2];
    float* out = (float*)d_out;

    norm_split_kernel<<<3 * B_ROWS, 256>>>(p, e, c);

    cudaFuncSetAttribute(gemm_kernel, cudaFuncAttributeMaxDynamicSharedMemorySize, SMEM_BYTES);
    gemm_kernel<<<(B_ROWS / MT) * (NCOLS / NT), 256, SMEM_BYTES>>>(out);

    lse_kernel<<<B_ROWS / 8, 256>>>(out + 1);
    loss_kernel<<<1, 256>>>(out);
}

// round 4
// speedup vs baseline: 2.5269x; 1.8686x over previous
#include <cuda_runtime.h>
#include <cuda_fp16.h>
#include <cstdint>

#define DI __device__ __forceinline__

static constexpr int B_ROWS = 8192;
static constexpr int DIM    = 1024;
static constexpr int NCOLS  = 16384;   // 2*B
static constexpr int NTILE  = 128;     // NCOLS / NT

// GEMM tiling
static constexpr int MT = 128;
static constexpr int NT = 128;
static constexpr int KC = 64;                  // fp16 elems per K chunk (128 B rows)
static constexpr int NCHUNK = DIM / KC;        // 16

// stage: A, B each 128 rows x 128 bytes = 16 KB
static constexpr int TILE_BYTES  = 128 * 128;          // 16384
static constexpr int STAGE_BYTES = 2 * TILE_BYTES;     // 32 KB
static constexpr int NSTAGE      = 3;
static constexpr int SMEM_BYTES  = NSTAGE * STAGE_BYTES;  // 96 KB

// -------- scratch (static device arrays; no allocation) --------
__device__ __half g_a[B_ROWS * DIM];              // premise, x20/||.||
__device__ __half g_b[(size_t)NCOLS * DIM];       // entail rows then contra rows
__device__ float  g_part[(size_t)B_ROWS * NTILE]; // per (row, n-tile) sum of exp(sim-20)
__device__ float  g_rowloss[B_ROWS];

// -------- helpers --------
DI uint32_t smem_u32(const void* p) {
    uint32_t a;
    asm("{ .reg .u64 t; cvta.to.shared.u64 t, %1; cvt.u32.u64 %0, t; }" : "=r"(a) : "l"(p));
    return a;
}
DI uint32_t swz(uint32_t off) { return off ^ ((off >> 3) & 0x70); }

DI void cp_async16(uint32_t dst, const void* src) {
    asm volatile("cp.async.cg.shared.global [%0], [%1], 16;" :: "r"(dst), "l"(src) : "memory");
}
#define CP_COMMIT() asm volatile("cp.async.commit_group;" ::: "memory")
#define CP_WAIT(n)  asm volatile("cp.async.wait_group %0;" :: "n"(n) : "memory")

DI void ldsm4(uint32_t* r, uint32_t addr) {
    asm volatile("ldmatrix.sync.aligned.m8n8.x4.shared.b16 {%0,%1,%2,%3}, [%4];"
                 : "=r"(r[0]), "=r"(r[1]), "=r"(r[2]), "=r"(r[3]) : "r"(addr));
}

DI void mma_f16(float* c, const uint32_t* a, const uint32_t* b) {
    asm volatile(
        "mma.sync.aligned.m16n8k16.row.col.f32.f16.f16.f32 "
        "{%0,%1,%2,%3}, {%4,%5,%6,%7}, {%8,%9}, {%0,%1,%2,%3};"
        : "+f"(c[0]), "+f"(c[1]), "+f"(c[2]), "+f"(c[3])
        : "r"(a[0]), "r"(a[1]), "r"(a[2]), "r"(a[3]), "r"(b[0]), "r"(b[1]));
}

// -------- block reduce (sum) for 256-thread blocks --------
DI float block_sum256(float v) {
    __shared__ float red[8];
    #pragma unroll
    for (int o = 16; o; o >>= 1) v += __shfl_xor_sync(0xFFFFFFFFu, v, o);
    if ((threadIdx.x & 31) == 0) red[threadIdx.x >> 5] = v;
    __syncthreads();
    if (threadIdx.x < 8) {
        v = red[threadIdx.x];
        #pragma unroll
        for (int o = 4; o; o >>= 1) v += __shfl_xor_sync(0xFFu, v, o);
        if (threadIdx.x == 0) red[0] = v;
    }
    __syncthreads();
    return red[0];
}

// ============ Kernel 1: L2-normalize rows -> fp16 ============
// premise scaled by 1/TEMP=20 so the GEMM emits sims directly.
__global__ void __launch_bounds__(256) norm_split_kernel(
    const float* __restrict__ p, const float* __restrict__ e, const float* __restrict__ c)
{
    int row = blockIdx.x;
    const float* src;
    __half* dst;
    bool is_a = (row < B_ROWS);
    if (is_a) {
        src = p + (size_t)row * DIM;
        dst = g_a + (size_t)row * DIM;
    } else if (row < 2 * B_ROWS) {
        src = e + (size_t)(row - B_ROWS) * DIM;
        dst = g_b + (size_t)(row - B_ROWS) * DIM;
    } else {
        src = c + (size_t)(row - 2 * B_ROWS) * DIM;
        dst = g_b + (size_t)(row - B_ROWS) * DIM;   // contra after entail
    }

    float4 x = reinterpret_cast<const float4*>(src)[threadIdx.x];
    float ss = x.x * x.x + x.y * x.y + x.z * x.z + x.w * x.w;
    float tot = block_sum256(ss);
    float scale = (is_a ? 20.0f : 1.0f) / fmaxf(sqrtf(tot), 1e-8f);

    __half2 h0 = __floats2half2_rn(x.x * scale, x.y * scale);
    __half2 h1 = __floats2half2_rn(x.z * scale, x.w * scale);
    reinterpret_cast<__half2*>(dst)[threadIdx.x * 2 + 0] = h0;
    reinterpret_cast<__half2*>(dst)[threadIdx.x * 2 + 1] = h1;
}

// ============ Kernel 2: fp16 HMMA GEMM + fused partial LSE ============
// 256 threads, CTA tile 128x128, warp tile 64(M)x32(N), warps 2(M)x4(N),
// 3-stage cp.async pipeline, 2 CTAs/SM.
__global__ void __launch_bounds__(256, 2) gemm_kernel(float* __restrict__ out) {
    extern __shared__ char smem[];
    uint32_t sb = smem_u32(smem);
    int tid = threadIdx.x, w = tid >> 5, lane = tid & 31;

    // supertile swizzle: groups of 8 M-tiles, sweep N within a group
    int sid = blockIdx.x;
    int group  = sid >> 10;        // / (8*128)
    int within = sid & 1023;
    int mt = (group << 3) + (within & 7);
    int nt = within >> 3;
    int m0 = mt * MT, n0 = nt * NT;

    int wm = w & 1, wn = w >> 1;
    int warp_m = wm * 64, warp_n = wn * 32;

    float acc[4][4][4];
    #pragma unroll
    for (int a = 0; a < 4; a++)
        #pragma unroll
        for (int b = 0; b < 4; b++)
            #pragma unroll
            for (int k = 0; k < 4; k++) acc[a][b][k] = 0.0f;

    // ---- stage loader (8 cp.async of 16B per thread) ----
    #define LOAD_STAGE(chunk_) do {                                              \
        uint32_t stage_ = sb + ((chunk_) % NSTAGE) * STAGE_BYTES;                 \
        int k0_ = (chunk_) * KC;                                                  \
        _Pragma("unroll")                                                         \
        for (int i_ = 0; i_ < 8; i_++) {                                          \
            int q_ = tid + i_ * 256;                                              \
            int half_ = q_ >> 10; int idx_ = q_ & 1023;                           \
            int r_ = idx_ >> 3, kc_ = idx_ & 7;                                   \
            const __half* src_ = half_                                            \
                ? g_b + (size_t)(n0 + r_) * DIM + k0_ + kc_ * 8                   \
                : g_a + (size_t)(m0 + r_) * DIM + k0_ + kc_ * 8;                  \
            uint32_t dst_ = stage_ + half_ * TILE_BYTES + swz(r_ * 128 + kc_ * 16); \
            cp_async16(dst_, src_);                                               \
        }                                                                         \
        CP_COMMIT();                                                              \
    } while (0)

    LOAD_STAGE(0);
    LOAD_STAGE(1);

    for (int chunk = 0; chunk < NCHUNK; ++chunk) {
        if (chunk + 2 < NCHUNK) { LOAD_STAGE(chunk + 2); CP_WAIT(2); }
        else if (chunk + 1 < NCHUNK) { CP_WAIT(1); }
        else { CP_WAIT(0); }
        __syncthreads();

        uint32_t stage = sb + (chunk % NSTAGE) * STAGE_BYTES;
        uint32_t A = stage, Bt = stage + TILE_BYTES;

        int arow = warp_m + (lane & 15);
        int acol = (lane >> 4);                       // 0/1 -> k half
        int brow = (lane & 7) + ((lane >> 4) << 3);   // n within 16
        int bkh  = (lane >> 3) & 1;                   // k half

        #pragma unroll
        for (int kk = 0; kk < 4; kk++) {
            uint32_t a_r[4][4];
            #pragma unroll
            for (int mb = 0; mb < 4; mb++) {
                uint32_t off = swz((uint32_t)(arow + mb * 16) * 128 + kk * 32 + acol * 16);
                ldsm4(a_r[mb], A + off);
            }
            uint32_t b_r[2][4];
            #pragma unroll
            for (int p = 0; p < 2; p++) {
                uint32_t off = swz((uint32_t)(warp_n + p * 16 + brow) * 128 + kk * 32 + bkh * 16);
                ldsm4(b_r[p], Bt + off);
            }
            #pragma unroll
            for (int mb = 0; mb < 4; mb++)
                #pragma unroll
                for (int p = 0; p < 2; p++)
                    #pragma unroll
                    for (int sub = 0; sub < 2; sub++)
                        mma_f16(acc[mb][p * 2 + sub], a_r[mb], &b_r[p][sub * 2]);
        }
        __syncthreads();
    }

    // ---- epilogue 1: store sims ----
    float* o = out + 1;
    #pragma unroll
    for (int mb = 0; mb < 4; mb++) {
        int row = m0 + warp_m + mb * 16 + (lane >> 2);
        #pragma unroll
        for (int nb = 0; nb < 4; nb++) {
            int col = n0 + warp_n + nb * 8 + (lane & 3) * 2;
            float* p0 = o + (size_t)row * NCOLS + col;
            p0[0] = acc[mb][nb][0];
            p0[1] = acc[mb][nb][1];
            float* p1 = p0 + (size_t)8 * NCOLS;
            p1[0] = acc[mb][nb][2];
            p1[1] = acc[mb][nb][3];
        }
    }

    // ---- epilogue 2: fused partial logsumexp (sum of exp(sim - 20)) ----
    auto exp_poly = [](float v) -> float {       // e^v for v in [-45, ~1e-2]
        float t = v * 1.4426950408889634f;
        float fi = floorf(t);
        float f = t - fi;
        float p = 1.5403530393283441e-4f;
        p = p * f + 1.3333558146428443e-3f;
        p = p * f + 9.6181291076284771e-3f;
        p = p * f + 5.5504108664821580e-2f;
        p = p * f + 2.4022650695910071e-1f;
        p = p * f + 6.9314718055994531e-1f;
        p = p * f + 1.0f;
        return __int_as_float(((int)fi + 127) << 23) * p;
    };

    float s[8];
    #pragma unroll
    for (int i = 0; i < 8; i++) s[i] = 0.0f;
    #pragma unroll
    for (int mb = 0; mb < 4; mb++)
        #pragma unroll
        for (int nb = 0; nb < 4; nb++) {
            s[mb * 2 + 0] += exp_poly(acc[mb][nb][0] - 20.0f) + exp_poly(acc[mb][nb][1] - 20.0f);
            s[mb * 2 + 1] += exp_poly(acc[mb][nb][2] - 20.0f) + exp_poly(acc[mb][nb][3] - 20.0f);
        }
    #pragma unroll
    for (int i = 0; i < 8; i++) {
        s[i] += __shfl_xor_sync(0xFFFFFFFFu, s[i], 1);
        s[i] += __shfl_xor_sync(0xFFFFFFFFu, s[i], 2);
    }
    float* sred = reinterpret_cast<float*>(smem);   // [4 wn][128 rows]
    __syncthreads();
    if ((lane & 3) == 0) {
        #pragma unroll
        for (int mb = 0; mb < 4; mb++) {
            int rl = warp_m + mb * 16 + (lane >> 2);
            sred[wn * 128 + rl]     = s[mb * 2 + 0];
            sred[wn * 128 + rl + 8] = s[mb * 2 + 1];
        }
    }
    __syncthreads();
    if (tid < 128) {
        float t = (sred[tid] + sred[128 + tid]) + (sred[256 + tid] + sred[384 + tid]);
        g_part[(size_t)(m0 + tid) * NTILE + nt] = t;
    }
    #undef LOAD_STAGE
}

// ============ Kernel 3: row loss from partials ============
__global__ void __launch_bounds__(256) lse_kernel(const float* __restrict__ sims) {
    int w = threadIdx.x >> 5, lane = threadIdx.x & 31;
    int row = blockIdx.x * 8 + w;
    const float* pr = g_part + (size_t)row * NTILE;
    float s = (pr[lane] + pr[lane + 32]) + (pr[lane + 64] + pr[lane + 96]);
    #pragma unroll
    for (int o = 16; o; o >>= 1) s += __shfl_xor_sync(0xFFFFFFFFu, s, o);
    if (lane == 0) {
        float diag = sims[(size_t)row * NCOLS + row];
        g_rowloss[row] = 20.0f + logf(s) - diag;
    }
}

// ============ Kernel 4: deterministic mean ============
__global__ void __launch_bounds__(256) loss_kernel(float* __restrict__ out) {
    float s = 0.0f;
    for (int i = threadIdx.x; i < B_ROWS; i += 256) s += g_rowloss[i];
    float tot = block_sum256(s);
    if (threadIdx.x == 0) out[0] = tot * (1.0f / (float)B_ROWS);
}

// ============ launch ============
extern "C" void kernel_launch(void* const* d_in, const int* in_sizes, int n_in,
                              void* d_out, int out_size) {
    (void)in_sizes; (void)n_in; (void)out_size;
    const float* p = (const float*)d_in[0];
    const float* e = (const float*)d_in[1];
    const float* c = (const float*)d_in[2];
    float* out = (float*)d_out;

    norm_split_kernel<<<3 * B_ROWS, 256>>>(p, e, c);

    cudaFuncSetAttribute(gemm_kernel, cudaFuncAttributeMaxDynamicSharedMemorySize, SMEM_BYTES);
    gemm_kernel<<<(B_ROWS / MT) * (NCOLS / NT), 256, SMEM_BYTES>>>(out);

    lse_kernel<<<B_ROWS / 8, 256>>>(out + 1);
    loss_kernel<<<1, 256>>>(out);
}